// round 5
// baseline (speedup 1.0000x reference)
#include <cuda_runtime.h>
#include <cstdint>

#define N_NODES  100000
#define N_PAD    100096   // 782 * 128
#define N_EDGES  400000
#define N_GRAPHS 256
#define HID      256
#define LAYERS   3

typedef unsigned long long ull;

// ---------------- static device scratch (allocation-free rule) ----------------
__device__ float d_t  [(size_t)N_EDGES * HID];   // relu(attr@Wc + bc)
__device__ float d_e  [(size_t)N_EDGES * HID];   // final edge embeddings
__device__ float d_h  [(size_t)N_PAD   * HID];   // node features
__device__ float d_agg[(size_t)N_PAD   * HID];   // message aggregation
__device__ float d_t2 [(size_t)N_PAD   * HID];   // hidden after first conv GEMM
__device__ float d_Wc [4 * HID];                 // We @ W1  (fused edge MLP stage 1)
__device__ float d_bc [HID];                     // be @ W1 + b1
__device__ float d_bvec[HID];                    // head bias incl. bio part
__device__ float d_gm [N_GRAPHS * HID];          // pooled graph means
__device__ int   d_off[N_GRAPHS + 1];            // per-graph node ranges

// ---------------- f32x2 helpers ----------------
__device__ __forceinline__ ull pack2(float v) {
    ull r; asm("mov.b64 %0, {%1, %1};" : "=l"(r) : "f"(v)); return r;
}
__device__ __forceinline__ void ffma2(ull& d, ull a, ull b) {
    asm("fma.rn.f32x2 %0, %1, %2, %0;" : "+l"(d) : "l"(a), "l"(b));
}
__device__ __forceinline__ float2 up2(ull v) {
    float2 f; asm("mov.b64 {%0, %1}, %2;" : "=f"(f.x), "=f"(f.y) : "l"(v)); return f;
}

// ---------------- precompute: Wc = We@W1, bc = be@W1+b1, bvec = hb1 + bio@hW1[256:] ----
__global__ void k_pre(const float* __restrict__ We, const float* __restrict__ be,
                      const float* __restrict__ W1, const float* __restrict__ b1,
                      const float* __restrict__ bio, const float* __restrict__ hW1,
                      const float* __restrict__ hb1)
{
    int n = threadIdx.x;  // 0..255
    float s0 = 0.f, s1 = 0.f, s2 = 0.f, s3 = 0.f, sb = 0.f;
    for (int k = 0; k < 256; ++k) {
        float w = W1[k * 256 + n];
        s0 = fmaf(We[k],       w, s0);
        s1 = fmaf(We[256 + k], w, s1);
        s2 = fmaf(We[512 + k], w, s2);
        s3 = fmaf(We[768 + k], w, s3);
        sb = fmaf(be[k],       w, sb);
    }
    d_Wc[n] = s0; d_Wc[256 + n] = s1; d_Wc[512 + n] = s2; d_Wc[768 + n] = s3;
    d_bc[n] = sb + b1[n];
    float t = hb1[n];
    for (int j = 0; j < 512; ++j)
        t = fmaf(bio[j], hW1[(size_t)(256 + j) * 256 + n], t);
    d_bvec[n] = t;
}

// ---------------- per-graph offsets via binary search (batch is sorted) ----------------
__global__ void k_off(const int* __restrict__ batch)
{
    int g = threadIdx.x;
    if (g > N_GRAPHS) return;
    if (g == N_GRAPHS) { d_off[N_GRAPHS] = N_NODES; return; }
    int lo = 0, hi = N_NODES;
    while (lo < hi) {
        int mid = (lo + hi) >> 1;
        if (batch[mid] < g) lo = mid + 1; else hi = mid;
    }
    d_off[g] = lo;
}

// ---------------- node embedding gather (pad rows -> 0) ----------------
__global__ void k_embed(const int* __restrict__ x, const float* __restrict__ Wn,
                        float* __restrict__ h)
{
    int gid = blockIdx.x * 256 + threadIdx.x;
    int n = gid >> 6;
    int c4 = (gid & 63) << 2;
    float4 v = make_float4(0.f, 0.f, 0.f, 0.f);
    if (n < N_NODES) v = *(const float4*)&Wn[(size_t)x[n] * 256 + c4];
    *(float4*)&h[(size_t)n * 256 + c4] = v;
}

// ---------------- edge stage 1: t = relu(attr @ Wc + bc) ----------------
__global__ void k_edge1(const float* __restrict__ attr, float* __restrict__ t)
{
    int gid = blockIdx.x * 256 + threadIdx.x;
    int e = gid >> 6;
    int c4 = (gid & 63) << 2;
    float4 a  = *(const float4*)&attr[(size_t)e * 4];
    float4 w0 = *(const float4*)&d_Wc[c4];
    float4 w1 = *(const float4*)&d_Wc[256 + c4];
    float4 w2 = *(const float4*)&d_Wc[512 + c4];
    float4 w3 = *(const float4*)&d_Wc[768 + c4];
    float4 b  = *(const float4*)&d_bc[c4];
    float4 o;
    o.x = fmaxf(b.x + a.x * w0.x + a.y * w1.x + a.z * w2.x + a.w * w3.x, 0.f);
    o.y = fmaxf(b.y + a.x * w0.y + a.y * w1.y + a.z * w2.y + a.w * w3.y, 0.f);
    o.z = fmaxf(b.z + a.x * w0.z + a.y * w1.z + a.z * w2.z + a.w * w3.z, 0.f);
    o.w = fmaxf(b.w + a.x * w0.w + a.y * w1.w + a.z * w2.w + a.w * w3.w, 0.f);
    *(float4*)&t[(size_t)e * 256 + c4] = o;
}

// ---------------- scatter: agg[dst] += relu(h[src] + e)  (v4 float atomics) ----------------
__global__ void k_scatter(const int* __restrict__ ei, const float* __restrict__ e,
                          const float* __restrict__ h, float* __restrict__ agg)
{
    int gid = blockIdx.x * 256 + threadIdx.x;
    int eid = gid >> 6;
    int c4 = (gid & 63) << 2;
    int src = ei[eid];
    int dst = ei[N_EDGES + eid];
    float4 hv = *(const float4*)&h[(size_t)src * 256 + c4];
    float4 ev = *(const float4*)&e[(size_t)eid * 256 + c4];
    float4 m;
    m.x = fmaxf(hv.x + ev.x, 0.f);
    m.y = fmaxf(hv.y + ev.y, 0.f);
    m.z = fmaxf(hv.z + ev.z, 0.f);
    m.w = fmaxf(hv.w + ev.w, 0.f);
    float* p = &agg[(size_t)dst * 256 + c4];
    asm volatile("red.global.add.v4.f32 [%0], {%1, %2, %3, %4};"
                 :: "l"(p), "f"(m.x), "f"(m.y), "f"(m.z), "f"(m.w) : "memory");
}

// ---------------- GEMM: C[M,256] = epi(Aload @ W + bias) ----------------
// ALOAD: 0 = plain A; 1 = (1+eps)*A + Aagg     (GINE z)
// EPI:   0 = none; 1 = relu; 2 = edge struct scale
// BM=BN=128, BK=8, 256 threads, thread tile 8x8, M-paired FFMA2 accumulators.
template<int ALOAD, int EPI>
__global__ __launch_bounds__(256, 2)
void gemm256(const float* __restrict__ A, const float* __restrict__ Aagg,
             const float* __restrict__ epsp,
             const float* __restrict__ W, const float* __restrict__ bias,
             const float* __restrict__ eattr, const float* __restrict__ sscale,
             float* __restrict__ C)
{
    __shared__ __align__(16) float As[8][128];
    __shared__ __align__(16) float Bs[8][128];

    const int tid = threadIdx.x;
    const int tx = tid & 15;        // N direction (16)
    const int ty = tid >> 4;        // M direction (16)
    const size_t m0 = (size_t)blockIdx.x * 128;
    const int n0 = blockIdx.y * 128;

    const int la_m = tid >> 1;          // 0..127
    const int la_k = (tid & 1) * 4;     // 0 or 4
    const int lb_k = tid >> 5;          // 0..7
    const int lb_n = (tid & 31) * 4;    // 0..124

    float epsv = 1.0f;
    if constexpr (ALOAD == 1) epsv = 1.0f + *epsp;

    ull acc[4][8];
#pragma unroll
    for (int p = 0; p < 4; ++p)
#pragma unroll
        for (int j = 0; j < 8; ++j) acc[p][j] = 0ull;

    const float* Arow = A + (m0 + la_m) * 256;
    const float* Grow = nullptr;
    if constexpr (ALOAD == 1) Grow = Aagg + (m0 + la_m) * 256;

    float4 a4, b4;
    // prefetch iteration 0
    a4 = *(const float4*)(Arow + la_k);
    if constexpr (ALOAD == 1) {
        float4 g4 = *(const float4*)(Grow + la_k);
        a4.x = fmaf(epsv, a4.x, g4.x); a4.y = fmaf(epsv, a4.y, g4.y);
        a4.z = fmaf(epsv, a4.z, g4.z); a4.w = fmaf(epsv, a4.w, g4.w);
    }
    b4 = *(const float4*)(W + (size_t)lb_k * 256 + n0 + lb_n);

#pragma unroll 1
    for (int it = 0; it < 32; ++it) {
        __syncthreads();
        As[la_k + 0][la_m] = a4.x;
        As[la_k + 1][la_m] = a4.y;
        As[la_k + 2][la_m] = a4.z;
        As[la_k + 3][la_m] = a4.w;
        *(float4*)&Bs[lb_k][lb_n] = b4;
        __syncthreads();
        if (it < 31) {
            int k0 = (it + 1) * 8;
            a4 = *(const float4*)(Arow + k0 + la_k);
            if constexpr (ALOAD == 1) {
                float4 g4 = *(const float4*)(Grow + k0 + la_k);
                a4.x = fmaf(epsv, a4.x, g4.x); a4.y = fmaf(epsv, a4.y, g4.y);
                a4.z = fmaf(epsv, a4.z, g4.z); a4.w = fmaf(epsv, a4.w, g4.w);
            }
            b4 = *(const float4*)(W + (size_t)(k0 + lb_k) * 256 + n0 + lb_n);
        }
#pragma unroll
        for (int k = 0; k < 8; ++k) {
            ulonglong2 alo = *(const ulonglong2*)&As[k][ty * 4];        // rows m+0..3
            ulonglong2 ahi = *(const ulonglong2*)&As[k][64 + ty * 4];   // rows m+64..67
            float4 blo = *(const float4*)&Bs[k][tx * 4];
            float4 bhi = *(const float4*)&Bs[k][64 + tx * 4];
            float bv[8] = {blo.x, blo.y, blo.z, blo.w, bhi.x, bhi.y, bhi.z, bhi.w};
#pragma unroll
            for (int j = 0; j < 8; ++j) {
                ull bb = pack2(bv[j]);
                ffma2(acc[0][j], alo.x, bb);
                ffma2(acc[1][j], alo.y, bb);
                ffma2(acc[2][j], ahi.x, bb);
                ffma2(acc[3][j], ahi.y, bb);
            }
        }
    }

    // ---- epilogue ----
    float bvv[8];
#pragma unroll
    for (int j = 0; j < 8; ++j) {
        int col = (j < 4) ? (tx * 4 + j) : (64 + tx * 4 + (j - 4));
        bvv[j] = bias[n0 + col];
    }
    float sval = 1.f;
    if constexpr (EPI == 2) sval = *sscale;

#pragma unroll
    for (int p = 0; p < 4; ++p) {
        int rb = (p < 2) ? (ty * 4 + 2 * p) : (64 + ty * 4 + 2 * (p - 2));
        size_t r0 = m0 + rb;              // even row; r0+1 is odd row
        float o0[8], o1[8];
#pragma unroll
        for (int j = 0; j < 8; ++j) {
            float2 f = up2(acc[p][j]);
            o0[j] = f.x + bvv[j];
            o1[j] = f.y + bvv[j];
        }
        if constexpr (EPI == 1) {
#pragma unroll
            for (int j = 0; j < 8; ++j) { o0[j] = fmaxf(o0[j], 0.f); o1[j] = fmaxf(o1[j], 0.f); }
        }
        if constexpr (EPI == 2) {
            float s0 = (eattr[r0 * 4 + 1] > 0.f) ? sval : 1.f;
            float s1 = (eattr[(r0 + 1) * 4 + 1] > 0.f) ? sval : 1.f;
#pragma unroll
            for (int j = 0; j < 8; ++j) { o0[j] *= s0; o1[j] *= s1; }
        }
        *(float4*)&C[r0 * 256 + n0 + tx * 4]            = make_float4(o0[0], o0[1], o0[2], o0[3]);
        *(float4*)&C[r0 * 256 + n0 + 64 + tx * 4]       = make_float4(o0[4], o0[5], o0[6], o0[7]);
        *(float4*)&C[(r0 + 1) * 256 + n0 + tx * 4]      = make_float4(o1[0], o1[1], o1[2], o1[3]);
        *(float4*)&C[(r0 + 1) * 256 + n0 + 64 + tx * 4] = make_float4(o1[4], o1[5], o1[6], o1[7]);
    }
}

// ---------------- GraphNorm (in place), optional pooled-mean emit ----------------
__global__ void k_gnorm(float* __restrict__ h, const float* __restrict__ gamma,
                        const float* __restrict__ beta, const float* __restrict__ alpha,
                        int last)
{
    int g = blockIdx.x, c = threadIdx.x;
    int s = d_off[g], e = d_off[g + 1];
    int cnt = e - s;
    float inv = 1.0f / (float)(cnt > 0 ? cnt : 1);

    float mean = 0.f;
    for (int n = s; n < e; ++n) mean += h[(size_t)n * 256 + c];
    mean *= inv;
    float am = alpha[c] * mean;

    float var = 0.f;
    for (int n = s; n < e; ++n) {
        float dd = h[(size_t)n * 256 + c] - am;
        var = fmaf(dd, dd, var);
    }
    var *= inv;

    float sc = gamma[c] * rsqrtf(var + 1e-5f);
    float bt = beta[c];
    float gs = 0.f;
    for (int n = s; n < e; ++n) {
        float o = (h[(size_t)n * 256 + c] - am) * sc + bt;
        h[(size_t)n * 256 + c] = o;
        gs += o;
    }
    if (last) d_gm[g * 256 + c] = gs * inv;
}

// ---------------- head: out[g] = relu([g_mean, bio] @ W1 + b1) @ W2 + b2 ----------------
__global__ void k_head(const float* __restrict__ W1, const float* __restrict__ W2,
                       const float* __restrict__ b2, float* __restrict__ out)
{
    __shared__ float gs[256];
    __shared__ float red[256];
    int g = blockIdx.x, n = threadIdx.x;
    gs[n] = d_gm[g * 256 + n];
    __syncthreads();
    float s = d_bvec[n];
#pragma unroll 8
    for (int k = 0; k < 256; ++k)
        s = fmaf(gs[k], W1[(size_t)k * 256 + n], s);
    red[n] = fmaxf(s, 0.f) * W2[n];
    __syncthreads();
    for (int st = 128; st > 0; st >>= 1) {
        if (n < st) red[n] += red[n + st];
        __syncthreads();
    }
    if (n == 0) out[g] = red[0] + b2[0];
}

// ---------------- launch ----------------
extern "C" void kernel_launch(void* const* d_in, const int* in_sizes, int n_in,
                              void* d_out, int out_size)
{
    const int*   x     = (const int*)d_in[0];
    const int*   ei    = (const int*)d_in[1];
    const float* attr  = (const float*)d_in[2];
    const int*   batch = (const int*)d_in[3];
    const float* nodeW = (const float*)d_in[4];
    const float* eW    = (const float*)d_in[5];
    const float* eb    = (const float*)d_in[6];
    const float* mW1   = (const float*)d_in[7];
    const float* mb1   = (const float*)d_in[8];
    const float* mW2   = (const float*)d_in[9];
    const float* mb2   = (const float*)d_in[10];
    const float* ss    = (const float*)d_in[11];
    const float* cW1   = (const float*)d_in[12];
    const float* cb1   = (const float*)d_in[13];
    const float* cW2   = (const float*)d_in[14];
    const float* cb2   = (const float*)d_in[15];
    const float* ceps  = (const float*)d_in[16];
    const float* ngam  = (const float*)d_in[17];
    const float* nbet  = (const float*)d_in[18];
    const float* nalp  = (const float*)d_in[19];
    const float* bio   = (const float*)d_in[20];
    const float* hW1   = (const float*)d_in[21];
    const float* hb1   = (const float*)d_in[22];
    const float* hW2   = (const float*)d_in[23];
    const float* hb2   = (const float*)d_in[24];
    float* out = (float*)d_out;

    float *t, *e, *h, *agg, *t2;
    cudaGetSymbolAddress((void**)&t,   d_t);
    cudaGetSymbolAddress((void**)&e,   d_e);
    cudaGetSymbolAddress((void**)&h,   d_h);
    cudaGetSymbolAddress((void**)&agg, d_agg);
    cudaGetSymbolAddress((void**)&t2,  d_t2);

    k_pre<<<1, 256>>>(eW, eb, mW1, mb1, bio, hW1, hb1);
    k_off<<<1, N_GRAPHS + 1>>>(batch);
    k_embed<<<N_PAD / 4, 256>>>(x, nodeW, h);
    k_edge1<<<N_EDGES / 4, 256>>>(attr, t);

    dim3 ge(N_EDGES / 128, 2);
    gemm256<0, 2><<<ge, 256>>>(t, nullptr, nullptr, mW2, mb2, attr, ss, e);

    dim3 gn(N_PAD / 128, 2);
    for (int l = 0; l < LAYERS; ++l) {
        cudaMemsetAsync(agg, 0, (size_t)N_PAD * 256 * sizeof(float), 0);
        k_scatter<<<N_EDGES / 4, 256>>>(ei, e, h, agg);
        gemm256<1, 1><<<gn, 256>>>(h, agg, ceps + l,
                                   cW1 + (size_t)l * 65536, cb1 + (size_t)l * 256,
                                   nullptr, nullptr, t2);
        gemm256<0, 0><<<gn, 256>>>(t2, nullptr, nullptr,
                                   cW2 + (size_t)l * 65536, cb2 + (size_t)l * 256,
                                   nullptr, nullptr, h);
        k_gnorm<<<N_GRAPHS, 256>>>(h, ngam + (size_t)l * 256, nbet + (size_t)l * 256,
                                   nalp + (size_t)l * 256, l == LAYERS - 1);
    }
    k_head<<<N_GRAPHS, 256>>>(hW1, hW2, hb2, out);
}

// round 8
// speedup vs baseline: 1.1261x; 1.1261x over previous
#include <cuda_runtime.h>
#include <cuda_bf16.h>
#include <cstdint>

#define N_NODES  100000
#define N_PAD    100096   // 782 * 128
#define N_EDGES  400000
#define N_GRAPHS 256
#define HID      256
#define KB3      768      // bf16-triple K
#define LAYERS   3

typedef unsigned long long ull;
typedef __nv_bfloat16 bf16;

// ---------------- static device scratch (allocation-free rule) ----------------
__device__ bf16  d_tb [(size_t)N_EDGES * KB3];   // edge MLP stage-1 out, bf16 triple (hi,lo,hi)
__device__ float d_e  [(size_t)N_EDGES * HID];   // final edge embeddings (fp32)
__device__ float d_h  [(size_t)N_PAD   * HID];   // node features
__device__ float d_agg[(size_t)N_PAD   * HID];   // message aggregation
__device__ bf16  d_zb [(size_t)N_PAD   * KB3];   // GINE z, bf16 triple
__device__ bf16  d_t2b[(size_t)N_PAD   * KB3];   // relu(GEMM1) out, bf16 triple
__device__ bf16  d_Wt [7 * 256 * KB3];           // weights, n-major, triple (hi,hi,lo)
__device__ float d_Wc [4 * HID];                 // We @ W1
__device__ float d_bc [HID];                     // be @ W1 + b1
__device__ float d_bvec[HID];                    // head bias incl. bio part
__device__ float d_gm [N_GRAPHS * HID];          // pooled graph means
__device__ int   d_off[N_GRAPHS + 1];            // per-graph node ranges

// ---------------- helpers ----------------
__device__ __forceinline__ void bsplit(float v, float& h, float& l) {
    bf16 hb = __float2bfloat16(v);
    h = __bfloat162float(hb);
    l = v - h;
}
__device__ __forceinline__ unsigned bfpack(float a, float b) {
    __nv_bfloat162 t = __floats2bfloat162_rn(a, b);   // x=a (low addr), y=b
    return *reinterpret_cast<unsigned*>(&t);
}

// ---------------- precompute: Wc = We@W1, bc = be@W1+b1, bvec = hb1 + bio@hW1[256:] ----
__global__ void k_pre(const float* __restrict__ We, const float* __restrict__ be,
                      const float* __restrict__ W1, const float* __restrict__ b1,
                      const float* __restrict__ bio, const float* __restrict__ hW1,
                      const float* __restrict__ hb1)
{
    int n = threadIdx.x;
    float s0 = 0.f, s1 = 0.f, s2 = 0.f, s3 = 0.f, sb = 0.f;
    for (int k = 0; k < 256; ++k) {
        float w = W1[k * 256 + n];
        s0 = fmaf(We[k],       w, s0);
        s1 = fmaf(We[256 + k], w, s1);
        s2 = fmaf(We[512 + k], w, s2);
        s3 = fmaf(We[768 + k], w, s3);
        sb = fmaf(be[k],       w, sb);
    }
    d_Wc[n] = s0; d_Wc[256 + n] = s1; d_Wc[512 + n] = s2; d_Wc[768 + n] = s3;
    d_bc[n] = sb + b1[n];
    float t = hb1[n];
    for (int j = 0; j < 512; ++j)
        t = fmaf(bio[j], hW1[(size_t)(256 + j) * 256 + n], t);
    d_bvec[n] = t;
}

// ---------------- weight convert: W [256k,256n] fp32 -> Wt [256n, 768] triple (hi,hi,lo) ----
__global__ void k_wcvt(const float* __restrict__ W, bf16* __restrict__ Wt)
{
    int id = blockIdx.x * 256 + threadIdx.x;   // 65536
    int k = id >> 8, n = id & 255;
    float v = W[id];
    float hf, lf; bsplit(v, hf, lf);
    bf16 h = __float2bfloat16(hf);
    bf16 l = __float2bfloat16(lf);
    size_t base = (size_t)n * KB3 + 3 * k;
    Wt[base] = h; Wt[base + 1] = h; Wt[base + 2] = l;
}

// ---------------- per-graph offsets via binary search (batch is sorted) ----------------
__global__ void k_off(const int* __restrict__ batch)
{
    int g = threadIdx.x;
    if (g > N_GRAPHS) return;
    if (g == N_GRAPHS) { d_off[N_GRAPHS] = N_NODES; return; }
    int lo = 0, hi = N_NODES;
    while (lo < hi) {
        int mid = (lo + hi) >> 1;
        if (batch[mid] < g) lo = mid + 1; else hi = mid;
    }
    d_off[g] = lo;
}

// ---------------- node embedding gather (pad rows -> 0) ----------------
__global__ void k_embed(const int* __restrict__ x, const float* __restrict__ Wn,
                        float* __restrict__ h)
{
    int gid = blockIdx.x * 256 + threadIdx.x;
    int n = gid >> 6;
    int c4 = (gid & 63) << 2;
    float4 v = make_float4(0.f, 0.f, 0.f, 0.f);
    if (n < N_NODES) v = *(const float4*)&Wn[(size_t)x[n] * 256 + c4];
    *(float4*)&h[(size_t)n * 256 + c4] = v;
}

// ---------------- edge stage 1: t = relu(attr @ Wc + bc) -> bf16 triple (hi,lo,hi) ----------------
__global__ void k_edge1(const float* __restrict__ attr, bf16* __restrict__ tb)
{
    int gid = blockIdx.x * 256 + threadIdx.x;
    int e = gid >> 6;
    int c4 = (gid & 63) << 2;
    float4 a  = *(const float4*)&attr[(size_t)e * 4];
    float4 w0 = *(const float4*)&d_Wc[c4];
    float4 w1 = *(const float4*)&d_Wc[256 + c4];
    float4 w2 = *(const float4*)&d_Wc[512 + c4];
    float4 w3 = *(const float4*)&d_Wc[768 + c4];
    float4 b  = *(const float4*)&d_bc[c4];
    float o0 = fmaxf(b.x + a.x * w0.x + a.y * w1.x + a.z * w2.x + a.w * w3.x, 0.f);
    float o1 = fmaxf(b.y + a.x * w0.y + a.y * w1.y + a.z * w2.y + a.w * w3.y, 0.f);
    float o2 = fmaxf(b.z + a.x * w0.z + a.y * w1.z + a.z * w2.z + a.w * w3.z, 0.f);
    float o3 = fmaxf(b.w + a.x * w0.w + a.y * w1.w + a.z * w2.w + a.w * w3.w, 0.f);
    float h0,l0,h1,l1,h2,l2,h3,l3;
    bsplit(o0,h0,l0); bsplit(o1,h1,l1); bsplit(o2,h2,l2); bsplit(o3,h3,l3);
    size_t base = (size_t)e * KB3 + 3 * c4;
    // layout: h0 l0 h0 | h1 l1 h1 | h2 l2 h2 | h3 l3 h3
    *(uint2*)&tb[base]     = make_uint2(bfpack(h0,l0), bfpack(h0,h1));
    *(uint2*)&tb[base + 4] = make_uint2(bfpack(l1,h1), bfpack(h2,l2));
    *(uint2*)&tb[base + 8] = make_uint2(bfpack(h2,h3), bfpack(l3,h3));
}

// ---------------- GINE combine: z = (1+eps)h + agg -> bf16 triple (hi,lo,hi) ----------------
__global__ void k_z(const float* __restrict__ h, const float* __restrict__ agg,
                    const float* __restrict__ epsp, bf16* __restrict__ zb)
{
    int gid = blockIdx.x * 256 + threadIdx.x;
    int n = gid >> 6;
    int c4 = (gid & 63) << 2;
    float epsv = 1.0f + *epsp;
    float4 hv = *(const float4*)&h[(size_t)n * 256 + c4];
    float4 av = *(const float4*)&agg[(size_t)n * 256 + c4];
    float z0 = fmaf(epsv, hv.x, av.x);
    float z1 = fmaf(epsv, hv.y, av.y);
    float z2 = fmaf(epsv, hv.z, av.z);
    float z3 = fmaf(epsv, hv.w, av.w);
    float h0,l0,h1,l1,h2,l2,h3,l3;
    bsplit(z0,h0,l0); bsplit(z1,h1,l1); bsplit(z2,h2,l2); bsplit(z3,h3,l3);
    size_t base = (size_t)n * KB3 + 3 * c4;
    *(uint2*)&zb[base]     = make_uint2(bfpack(h0,l0), bfpack(h0,h1));
    *(uint2*)&zb[base + 4] = make_uint2(bfpack(l1,h1), bfpack(h2,l2));
    *(uint2*)&zb[base + 8] = make_uint2(bfpack(h2,h3), bfpack(l3,h3));
}

// ---------------- scatter: agg[dst] += relu(h[src] + e)  (v4 float atomics) ----------------
__global__ void k_scatter(const int* __restrict__ ei, const float* __restrict__ e,
                          const float* __restrict__ h, float* __restrict__ agg)
{
    int gid = blockIdx.x * 256 + threadIdx.x;
    int eid = gid >> 6;
    int c4 = (gid & 63) << 2;
    int src = ei[eid];
    int dst = ei[N_EDGES + eid];
    float4 hv = *(const float4*)&h[(size_t)src * 256 + c4];
    float4 ev = *(const float4*)&e[(size_t)eid * 256 + c4];
    float4 m;
    m.x = fmaxf(hv.x + ev.x, 0.f);
    m.y = fmaxf(hv.y + ev.y, 0.f);
    m.z = fmaxf(hv.z + ev.z, 0.f);
    m.w = fmaxf(hv.w + ev.w, 0.f);
    float* p = &agg[(size_t)dst * 256 + c4];
    asm volatile("red.global.add.v4.f32 [%0], {%1, %2, %3, %4};"
                 :: "l"(p), "f"(m.x), "f"(m.y), "f"(m.z), "f"(m.w) : "memory");
}

// ---------------- bf16 HMMA GEMM: C[M,256] = epi(A[M,768] @ Bt^T + bias) ----------------
// A: [M, 768] bf16 triple (hi,lo,hi).  Bt: [256, 768] bf16 n-major triple (hi,hi,lo).
// EPI: 0 = none (Cf fp32); 1 = relu + bf16-triple out (Cb); 2 = struct scale (Cf fp32).
template<int EPI>
__global__ __launch_bounds__(256, 2)
void gemm_bf(const bf16* __restrict__ A, const bf16* __restrict__ Bt,
             const float* __restrict__ bias,
             const float* __restrict__ eattr, const float* __restrict__ sscale,
             float* __restrict__ Cf, bf16* __restrict__ Cb)
{
    __shared__ __align__(16) bf16 As[2][128][40];
    __shared__ __align__(16) bf16 Bs[2][128][40];

    const int tid  = threadIdx.x;
    const int wid  = tid >> 5, lane = tid & 31;
    const int wm   = wid >> 2, wn = wid & 3;      // 2 x 4 warps, tile 64x32
    const int g    = lane >> 2, q = lane & 3;
    const size_t m0 = (size_t)blockIdx.x * 128;
    const int n0   = blockIdx.y * 128;

    const int lrow = tid >> 2;          // 0..63
    const int lcol = (tid & 3) * 8;     // 0,8,16,24

    const bf16* Ag = A + (m0 + lrow) * KB3 + lcol;
    const bf16* Bg = Bt + (size_t)(n0 + lrow) * KB3 + lcol;

    float acc[4][4][4];
#pragma unroll
    for (int mt = 0; mt < 4; ++mt)
#pragma unroll
        for (int nt = 0; nt < 4; ++nt)
#pragma unroll
            for (int i = 0; i < 4; ++i) acc[mt][nt][i] = 0.f;

    uint4 ra0, ra1, rb0, rb1;
    ra0 = *(const uint4*)(Ag);
    ra1 = *(const uint4*)(Ag + (size_t)64 * KB3);
    rb0 = *(const uint4*)(Bg);
    rb1 = *(const uint4*)(Bg + (size_t)64 * KB3);
    *(uint4*)&As[0][lrow][lcol]      = ra0;
    *(uint4*)&As[0][lrow + 64][lcol] = ra1;
    *(uint4*)&Bs[0][lrow][lcol]      = rb0;
    *(uint4*)&Bs[0][lrow + 64][lcol] = rb1;
    __syncthreads();

#pragma unroll 1
    for (int it = 0; it < 24; ++it) {
        const int cur = it & 1;
        if (it < 23) {
            const bf16* Ap = Ag + (it + 1) * 32;
            const bf16* Bp = Bg + (it + 1) * 32;
            ra0 = *(const uint4*)(Ap);
            ra1 = *(const uint4*)(Ap + (size_t)64 * KB3);
            rb0 = *(const uint4*)(Bp);
            rb1 = *(const uint4*)(Bp + (size_t)64 * KB3);
        }
#pragma unroll
        for (int ks = 0; ks < 2; ++ks) {
            const int kk = ks * 16;
            unsigned a[4][4], b[4][2];
#pragma unroll
            for (int mt = 0; mt < 4; ++mt) {
                int r = wm * 64 + mt * 16 + g;
                a[mt][0] = *(const unsigned*)&As[cur][r][kk + 2 * q];
                a[mt][1] = *(const unsigned*)&As[cur][r + 8][kk + 2 * q];
                a[mt][2] = *(const unsigned*)&As[cur][r][kk + 2 * q + 8];
                a[mt][3] = *(const unsigned*)&As[cur][r + 8][kk + 2 * q + 8];
            }
#pragma unroll
            for (int nt = 0; nt < 4; ++nt) {
                int c = wn * 32 + nt * 8 + g;
                b[nt][0] = *(const unsigned*)&Bs[cur][c][kk + 2 * q];
                b[nt][1] = *(const unsigned*)&Bs[cur][c][kk + 2 * q + 8];
            }
#pragma unroll
            for (int mt = 0; mt < 4; ++mt)
#pragma unroll
                for (int nt = 0; nt < 4; ++nt)
                    asm volatile(
                        "mma.sync.aligned.m16n8k16.row.col.f32.bf16.bf16.f32 "
                        "{%0,%1,%2,%3}, {%4,%5,%6,%7}, {%8,%9}, {%0,%1,%2,%3};"
                        : "+f"(acc[mt][nt][0]), "+f"(acc[mt][nt][1]),
                          "+f"(acc[mt][nt][2]), "+f"(acc[mt][nt][3])
                        : "r"(a[mt][0]), "r"(a[mt][1]), "r"(a[mt][2]), "r"(a[mt][3]),
                          "r"(b[nt][0]), "r"(b[nt][1]));
        }
        if (it < 23) {
            const int nxt = cur ^ 1;
            *(uint4*)&As[nxt][lrow][lcol]      = ra0;
            *(uint4*)&As[nxt][lrow + 64][lcol] = ra1;
            *(uint4*)&Bs[nxt][lrow][lcol]      = rb0;
            *(uint4*)&Bs[nxt][lrow + 64][lcol] = rb1;
            __syncthreads();
        }
    }

    // ---- epilogue ----
    const float sval = (EPI == 2) ? *sscale : 1.f;
#pragma unroll
    for (int mt = 0; mt < 4; ++mt) {
        size_t r0 = m0 + wm * 64 + mt * 16 + g;
        size_t r1 = r0 + 8;
        float s0 = 1.f, s1 = 1.f;
        if (EPI == 2) {
            s0 = (eattr[r0 * 4 + 1] > 0.f) ? sval : 1.f;
            s1 = (eattr[r1 * 4 + 1] > 0.f) ? sval : 1.f;
        }
#pragma unroll
        for (int nt = 0; nt < 4; ++nt) {
            int c = n0 + wn * 32 + nt * 8 + 2 * q;
            float b0 = bias[c], b1 = bias[c + 1];
            float v00 = acc[mt][nt][0] + b0;
            float v01 = acc[mt][nt][1] + b1;
            float v10 = acc[mt][nt][2] + b0;
            float v11 = acc[mt][nt][3] + b1;
            if (EPI == 0) {
                *(float2*)&Cf[r0 * 256 + c] = make_float2(v00, v01);
                *(float2*)&Cf[r1 * 256 + c] = make_float2(v10, v11);
            } else if (EPI == 1) {
                v00 = fmaxf(v00, 0.f); v01 = fmaxf(v01, 0.f);
                v10 = fmaxf(v10, 0.f); v11 = fmaxf(v11, 0.f);
                float h0,l0,h1,l1;
                bsplit(v00, h0, l0); bsplit(v01, h1, l1);
                size_t p = r0 * KB3 + 3 * (size_t)c;
                *(unsigned*)&Cb[p]     = bfpack(h0, l0);
                *(unsigned*)&Cb[p + 2] = bfpack(h0, h1);
                *(unsigned*)&Cb[p + 4] = bfpack(l1, h1);
                bsplit(v10, h0, l0); bsplit(v11, h1, l1);
                p = r1 * KB3 + 3 * (size_t)c;
                *(unsigned*)&Cb[p]     = bfpack(h0, l0);
                *(unsigned*)&Cb[p + 2] = bfpack(h0, h1);
                *(unsigned*)&Cb[p + 4] = bfpack(l1, h1);
            } else {
                *(float2*)&Cf[r0 * 256 + c] = make_float2(v00 * s0, v01 * s0);
                *(float2*)&Cf[r1 * 256 + c] = make_float2(v10 * s1, v11 * s1);
            }
        }
    }
}

// ---------------- GraphNorm (in place), optional pooled-mean emit ----------------
__global__ void k_gnorm(float* __restrict__ h, const float* __restrict__ gamma,
                        const float* __restrict__ beta, const float* __restrict__ alpha,
                        int last)
{
    int g = blockIdx.x, c = threadIdx.x;
    int s = d_off[g], e = d_off[g + 1];
    int cnt = e - s;
    float inv = 1.0f / (float)(cnt > 0 ? cnt : 1);

    float mean = 0.f;
    for (int n = s; n < e; ++n) mean += h[(size_t)n * 256 + c];
    mean *= inv;
    float am = alpha[c] * mean;

    float var = 0.f;
    for (int n = s; n < e; ++n) {
        float dd = h[(size_t)n * 256 + c] - am;
        var = fmaf(dd, dd, var);
    }
    var *= inv;

    float sc = gamma[c] * rsqrtf(var + 1e-5f);
    float bt = beta[c];
    float gs = 0.f;
    for (int n = s; n < e; ++n) {
        float o = (h[(size_t)n * 256 + c] - am) * sc + bt;
        h[(size_t)n * 256 + c] = o;
        gs += o;
    }
    if (last) d_gm[g * 256 + c] = gs * inv;
}

// ---------------- head: out[g] = relu([g_mean, bio] @ W1 + b1) @ W2 + b2 ----------------
__global__ void k_head(const float* __restrict__ W1, const float* __restrict__ W2,
                       const float* __restrict__ b2, float* __restrict__ out)
{
    __shared__ float gs[256];
    __shared__ float red[256];
    int g = blockIdx.x, n = threadIdx.x;
    gs[n] = d_gm[g * 256 + n];
    __syncthreads();
    float s = d_bvec[n];
#pragma unroll 8
    for (int k = 0; k < 256; ++k)
        s = fmaf(gs[k], W1[(size_t)k * 256 + n], s);
    red[n] = fmaxf(s, 0.f) * W2[n];
    __syncthreads();
    for (int st = 128; st > 0; st >>= 1) {
        if (n < st) red[n] += red[n + st];
        __syncthreads();
    }
    if (n == 0) out[g] = red[0] + b2[0];
}

// ---------------- launch ----------------
extern "C" void kernel_launch(void* const* d_in, const int* in_sizes, int n_in,
                              void* d_out, int out_size)
{
    const int*   x     = (const int*)d_in[0];
    const int*   ei    = (const int*)d_in[1];
    const float* attr  = (const float*)d_in[2];
    const int*   batch = (const int*)d_in[3];
    const float* nodeW = (const float*)d_in[4];
    const float* eW    = (const float*)d_in[5];
    const float* eb    = (const float*)d_in[6];
    const float* mW1   = (const float*)d_in[7];
    const float* mb1   = (const float*)d_in[8];
    const float* mW2   = (const float*)d_in[9];
    const float* mb2   = (const float*)d_in[10];
    const float* ss    = (const float*)d_in[11];
    const float* cW1   = (const float*)d_in[12];
    const float* cb1   = (const float*)d_in[13];
    const float* cW2   = (const float*)d_in[14];
    const float* cb2   = (const float*)d_in[15];
    const float* ceps  = (const float*)d_in[16];
    const float* ngam  = (const float*)d_in[17];
    const float* nbet  = (const float*)d_in[18];
    const float* nalp  = (const float*)d_in[19];
    const float* bio   = (const float*)d_in[20];
    const float* hW1   = (const float*)d_in[21];
    const float* hb1   = (const float*)d_in[22];
    const float* hW2   = (const float*)d_in[23];
    const float* hb2   = (const float*)d_in[24];
    float* out = (float*)d_out;

    bf16 *tb, *zb, *t2b, *Wt;
    float *e, *h, *agg;
    cudaGetSymbolAddress((void**)&tb,  d_tb);
    cudaGetSymbolAddress((void**)&e,   d_e);
    cudaGetSymbolAddress((void**)&h,   d_h);
    cudaGetSymbolAddress((void**)&agg, d_agg);
    cudaGetSymbolAddress((void**)&zb,  d_zb);
    cudaGetSymbolAddress((void**)&t2b, d_t2b);
    cudaGetSymbolAddress((void**)&Wt,  d_Wt);

    const size_t WSTRIDE = (size_t)256 * KB3;

    k_pre<<<1, 256>>>(eW, eb, mW1, mb1, bio, hW1, hb1);
    k_off<<<1, N_GRAPHS + 1>>>(batch);
    k_wcvt<<<256, 256>>>(mW2, Wt);                       // slot 0: edge MLP W2
    for (int l = 0; l < LAYERS; ++l) {
        k_wcvt<<<256, 256>>>(cW1 + (size_t)l * 65536, Wt + (1 + l) * WSTRIDE);
        k_wcvt<<<256, 256>>>(cW2 + (size_t)l * 65536, Wt + (4 + l) * WSTRIDE);
    }
    k_embed<<<N_PAD / 4, 256>>>(x, nodeW, h);
    k_edge1<<<N_EDGES / 4, 256>>>(attr, tb);

    dim3 ge(N_EDGES / 128, 2);
    gemm_bf<2><<<ge, 256>>>(tb, Wt, mb2, attr, ss, e, nullptr);

    dim3 gn(N_PAD / 128, 2);
    for (int l = 0; l < LAYERS; ++l) {
        cudaMemsetAsync(agg, 0, (size_t)N_PAD * 256 * sizeof(float), 0);
        k_scatter<<<N_EDGES / 4, 256>>>(ei, e, h, agg);
        k_z<<<N_PAD / 4, 256>>>(h, agg, ceps + l, zb);
        gemm_bf<1><<<gn, 256>>>(zb, Wt + (1 + l) * WSTRIDE, cb1 + (size_t)l * 256,
                                nullptr, nullptr, nullptr, t2b);
        gemm_bf<0><<<gn, 256>>>(t2b, Wt + (4 + l) * WSTRIDE, cb2 + (size_t)l * 256,
                                nullptr, nullptr, h, nullptr);
        k_gnorm<<<N_GRAPHS, 256>>>(h, ngam + (size_t)l * 256, nbet + (size_t)l * 256,
                                   nalp + (size_t)l * 256, l == LAYERS - 1);
    }
    k_head<<<N_GRAPHS, 256>>>(hW1, hW2, hb2, out);
}